// round 8
// baseline (speedup 1.0000x reference)
#include <cuda_runtime.h>
#include <math.h>

// x (B=32, C=256, H=64, W=64) fp32; s=mean_c(x); h=relu(s*w1+b1)[16];
// scale=sigmoid(w2@h+b2); out=x*scale
// Identity: z[c] = w2[c]@relu(s*w1+b1)+b2[c] is piecewise-linear in s:
//   z[c] = A[c,i]*s + B[c,i],  i = #{k : s > t_k},  t_k = -b1[k]/w1[k]
// R8: software pipelining across tiles — tile n+1's loads are issued into a
// second register set BEFORE tile n's reduce/compute, so DRAM stays fed
// through the barriers. 256 thr, 2 CTAs/SM (128-reg cap), persistent grid.

#define B_    32
#define CH    256
#define HW4   1024          // 4096/4 float4 per (b,c) row
#define HID   16
#define P4    8             // float4 pixels per tile (32 px)
#define TPB   256
#define NGRP  32            // channel groups
#define CPT   8             // channels per thread -> v[8] = 32 regs
#define NTILE 4096          // 32 images * (1024/8) tiles
#define GRID  296           // 2 persistent CTAs per SM * 148
#define RPAD  9             // partials row pad (odd stride: conflict-free)

__global__ __launch_bounds__(TPB, 2)
void pse_fused_kernel(const float4* __restrict__ x,
                      const float*  __restrict__ w1,
                      const float*  __restrict__ b1,
                      const float*  __restrict__ w2,
                      const float*  __restrict__ b2,
                      float4* __restrict__ out)
{
    __shared__ float2 AB[CH * 17];          // 34,816 B piecewise-linear table
    __shared__ float  red_x[NGRP * RPAD];   // SoA partials [group][pixel]
    __shared__ float  red_y[NGRP * RPAD];
    __shared__ float  red_z[NGRP * RPAD];
    __shared__ float  red_w[NGRP * RPAD];
    __shared__ float4 s4b[P4];
    __shared__ int4   i4b[P4];
    __shared__ float  us[HID];
    __shared__ float  reps[HID + 1];

    const int t = threadIdx.x;
    const int q = t & (P4 - 1);             // float4-pixel 0..7
    const int g = t >> 3;                   // channel group 0..31
    const float INF = __int_as_float(0x7f800000);

    // ---------- per-CTA prologue: build piecewise-linear table ----------
    if (t < HID) {
        float w = w1[t], b = b1[t];
        float myth = (w != 0.0f) ? (-b / w) : INF;
        int rank = 0;
        #pragma unroll
        for (int k = 0; k < HID; k++) {
            float wk = w1[k], bk = b1[k];
            float tk = (wk != 0.0f) ? (-bk / wk) : INF;
            rank += (tk < myth) || (tk == myth && k < t);
        }
        us[rank] = myth;
    }
    __syncthreads();
    if (t < HID + 1) {
        float lo = (t == 0)   ? -INF : us[t - 1];
        float hi = (t == HID) ?  INF : us[t];
        bool flo = isfinite(lo), fhi = isfinite(hi);
        if (!flo && !fhi)      { lo = -1.0f; hi = 1.0f; }
        else if (!flo)         lo = hi - 2.0f;
        else if (!fhi)         hi = lo + 2.0f;
        reps[t] = 0.5f * (lo + hi);
    }
    __syncthreads();
    {   // one channel per thread (TPB == CH)
        const int c = t;
        float w2r[HID];
        #pragma unroll
        for (int k = 0; k < HID; k++) w2r[k] = w2[c * HID + k];
        const float bc = b2[c];
        for (int i = 0; i < 17; i++) {
            const float rep = reps[i];
            float a = 0.0f, bb = bc;
            #pragma unroll
            for (int k = 0; k < HID; k++) {
                float wk = w1[k], bk = b1[k];
                if (fmaf(rep, wk, bk) > 0.0f) {   // unit k active on interval i
                    a  = fmaf(w2r[k], wk, a);
                    bb = fmaf(w2r[k], bk, bb);
                }
            }
            AB[c * 17 + i] = make_float2(a, bb);
        }
    }
    __syncthreads();

    // ---------- software-pipelined persistent tile loop ----------
    // Per-thread gmem offset for a given tile's base pointer.
    // tile -> img = tile>>7, base4 = (tile&127)<<3
    // elem offset = img*CH*HW4 + base4 + (g + j*NGRP)*HW4 + q

    int tile = blockIdx.x;
    float4 v[CPT];                            // current tile's x (in flight)
    {
        const size_t off0 = (size_t)(tile >> 7) * CH * HW4
                          + ((tile & 127) << 3) + (size_t)g * HW4 + q;
        #pragma unroll
        for (int j = 0; j < CPT; j++)
            v[j] = __ldcs(&x[off0 + (size_t)j * NGRP * HW4]);
    }

    for (; tile < NTILE; tile += GRID) {
        const int next = tile + GRID;

        // ---- prefetch NEXT tile's loads (independent; issued before syncs)
        float4 vn[CPT];
        if (next < NTILE) {
            const size_t offn = (size_t)(next >> 7) * CH * HW4
                              + ((next & 127) << 3) + (size_t)g * HW4 + q;
            #pragma unroll
            for (int j = 0; j < CPT; j++)
                vn[j] = __ldcs(&x[offn + (size_t)j * NGRP * HW4]);
        }

        // ---- pass 1: sums of current tile (v was prefetched last iter) ----
        float4 s = make_float4(0.f, 0.f, 0.f, 0.f);
        #pragma unroll
        for (int j = 0; j < CPT; j++) {
            s.x += v[j].x; s.y += v[j].y; s.z += v[j].z; s.w += v[j].w;
        }
        red_x[g * RPAD + q] = s.x;
        red_y[g * RPAD + q] = s.y;
        red_z[g * RPAD + q] = s.z;
        red_w[g * RPAD + q] = s.w;
        __syncthreads();

        // ---- reduce: warp w owns pixel w; lane l reads group-l partial ----
        {
            const int w = t >> 5, l = t & 31;
            float ax = red_x[l * RPAD + w];   // stride 9: conflict-free
            float ay = red_y[l * RPAD + w];
            float az = red_z[l * RPAD + w];
            float aw = red_w[l * RPAD + w];
            #pragma unroll
            for (int m = 1; m <= 16; m <<= 1) {
                ax += __shfl_xor_sync(0xffffffffu, ax, m);
                ay += __shfl_xor_sync(0xffffffffu, ay, m);
                az += __shfl_xor_sync(0xffffffffu, az, m);
                aw += __shfl_xor_sync(0xffffffffu, aw, m);
            }
            if (l == 0) {
                const float inv = 1.0f / (float)CH;
                float4 sv = make_float4(ax * inv, ay * inv, az * inv, aw * inv);
                int4 iv = make_int4(0, 0, 0, 0);
                #pragma unroll
                for (int k = 0; k < HID; k++) {
                    const float tk = us[k];
                    iv.x += (sv.x > tk); iv.y += (sv.y > tk);
                    iv.z += (sv.z > tk); iv.w += (sv.w > tk);
                }
                s4b[w] = sv; i4b[w] = iv;
            }
        }
        __syncthreads();

        // ---- pass 2: compute from registers + smem table, store ----
        const float4 sv = s4b[q];
        const int4   iv = i4b[q];
        {
            const size_t off0 = (size_t)(tile >> 7) * CH * HW4
                              + ((tile & 127) << 3) + (size_t)g * HW4 + q;
            #pragma unroll
            for (int j = 0; j < CPT; j++) {
                const int c = g + j * NGRP;
                const float2* row = AB + c * 17;
                const float2 a0 = row[iv.x], a1 = row[iv.y],
                             a2 = row[iv.z], a3 = row[iv.w];
                const float z0 = fmaf(a0.x, sv.x, a0.y);
                const float z1 = fmaf(a1.x, sv.y, a1.y);
                const float z2 = fmaf(a2.x, sv.z, a2.y);
                const float z3 = fmaf(a3.x, sv.w, a3.y);
                float4 o;
                o.x = __fdividef(v[j].x, 1.0f + __expf(-z0));
                o.y = __fdividef(v[j].y, 1.0f + __expf(-z1));
                o.z = __fdividef(v[j].z, 1.0f + __expf(-z2));
                o.w = __fdividef(v[j].w, 1.0f + __expf(-z3));
                __stcs(&out[off0 + (size_t)j * NGRP * HW4], o);
            }
        }

        // ---- rotate pipeline ----
        #pragma unroll
        for (int j = 0; j < CPT; j++) v[j] = vn[j];
        // next iteration's smem writes are fenced by its own __syncthreads()
    }
}

extern "C" void kernel_launch(void* const* d_in, const int* in_sizes, int n_in,
                              void* d_out, int out_size)
{
    pse_fused_kernel<<<GRID, TPB>>>((const float4*)d_in[0],
                                    (const float*)d_in[1],
                                    (const float*)d_in[2],
                                    (const float*)d_in[3],
                                    (const float*)d_in[4],
                                    (float4*)d_out);
}

// round 10
// speedup vs baseline: 1.0605x; 1.0605x over previous
#include <cuda_runtime.h>
#include <math.h>

// x (B=32, C=256, H=64, W=64) fp32; s=mean_c(x); h=relu(s*w1+b1)[16];
// scale=sigmoid(w2@h+b2); out=x*scale
// Identity: z[c] = w2[c]@relu(s*w1+b1)+b2[c] is piecewise-linear in s:
//   z[c] = A[c,i]*s + B[c,i],  i = #{k : s > t_k},  t_k = -b1[k]/w1[k]
// R10: R9 design with the tile->offset decomposition FIXED for P4=16
// (64 tiles/image: img = tile>>6, base4 = (tile&63)<<4). R9 shipped R8's
// P4=8 split (>>7/&127) which scrambled the image mapping.

#define B_    32
#define CH    256
#define HW4   1024          // 4096/4 float4 per (b,c) row
#define HID   16
#define P4    16            // float4 pixels per tile (64 px)
#define TPB   512
#define NGRP  32            // channel groups (t>>4)
#define CPT   8             // channels per thread -> v[8] = 32 regs
#define NTILE 2048          // 32 images * 64 tiles/image
#define GRID  296           // 2 persistent CTAs per SM * 148
#define RPAD  17            // partials row pad (odd stride: conflict-free)

__global__ __launch_bounds__(TPB, 2)
void pse_fused_kernel(const float4* __restrict__ x,
                      const float*  __restrict__ w1,
                      const float*  __restrict__ b1,
                      const float*  __restrict__ w2,
                      const float*  __restrict__ b2,
                      float4* __restrict__ out)
{
    __shared__ float2 AB[CH * 17];          // 34,816 B piecewise-linear table
    __shared__ float  red_x[NGRP * RPAD];   // SoA partials [group][pixel]
    __shared__ float  red_y[NGRP * RPAD];
    __shared__ float  red_z[NGRP * RPAD];
    __shared__ float  red_w[NGRP * RPAD];
    __shared__ float4 s4b[P4];
    __shared__ int4   i4b[P4];
    __shared__ float  us[HID];
    __shared__ float  reps[HID + 1];

    const int t = threadIdx.x;
    const int q = t & (P4 - 1);             // float4-pixel 0..15
    const int g = t >> 4;                   // channel group 0..31
    const float INF = __int_as_float(0x7f800000);

    // ---------- per-CTA prologue: build piecewise-linear table ----------
    if (t < HID) {
        float w = w1[t], b = b1[t];
        float myth = (w != 0.0f) ? (-b / w) : INF;
        int rank = 0;
        #pragma unroll
        for (int k = 0; k < HID; k++) {
            float wk = w1[k], bk = b1[k];
            float tk = (wk != 0.0f) ? (-bk / wk) : INF;
            rank += (tk < myth) || (tk == myth && k < t);
        }
        us[rank] = myth;
    }
    __syncthreads();
    if (t < HID + 1) {
        float lo = (t == 0)   ? -INF : us[t - 1];
        float hi = (t == HID) ?  INF : us[t];
        bool flo = isfinite(lo), fhi = isfinite(hi);
        if (!flo && !fhi)      { lo = -1.0f; hi = 1.0f; }
        else if (!flo)         lo = hi - 2.0f;
        else if (!fhi)         hi = lo + 2.0f;
        reps[t] = 0.5f * (lo + hi);
    }
    __syncthreads();
    {   // 512 threads, 2 per channel: thread handles intervals i%2 == t&1
        const int c = t >> 1;
        const int half = t & 1;
        float w2r[HID];
        #pragma unroll
        for (int k = 0; k < HID; k++) w2r[k] = w2[c * HID + k];
        const float bc = b2[c];
        for (int i = half; i < 17; i += 2) {
            const float rep = reps[i];
            float a = 0.0f, bb = bc;
            #pragma unroll
            for (int k = 0; k < HID; k++) {
                float wk = w1[k], bk = b1[k];
                if (fmaf(rep, wk, bk) > 0.0f) {   // unit k active on interval i
                    a  = fmaf(w2r[k], wk, a);
                    bb = fmaf(w2r[k], bk, bb);
                }
            }
            AB[c * 17 + i] = make_float2(a, bb);
        }
    }
    __syncthreads();

    // ---------- persistent tile loop (32-bit addressing) ----------
    const unsigned gq_off = (unsigned)g * HW4 + (unsigned)q;

    for (int tile = blockIdx.x; tile < NTILE; tile += GRID) {
        // 64 tiles per image: img = tile>>6, base4 = (tile&63)*P4
        const unsigned off0 = (unsigned)(tile >> 6) * (CH * HW4)
                            + ((unsigned)(tile & 63) << 4) + gq_off;

        // pass 1: 8 independent coalesced LDG.128 into regs (kept live)
        float4 v[CPT];
        #pragma unroll
        for (int j = 0; j < CPT; j++)
            v[j] = __ldcs(&x[off0 + (unsigned)j * (NGRP * HW4)]);

        float4 s = make_float4(0.f, 0.f, 0.f, 0.f);
        #pragma unroll
        for (int j = 0; j < CPT; j++) {
            s.x += v[j].x; s.y += v[j].y; s.z += v[j].z; s.w += v[j].w;
        }
        red_x[g * RPAD + q] = s.x;
        red_y[g * RPAD + q] = s.y;
        red_z[g * RPAD + q] = s.z;
        red_w[g * RPAD + q] = s.w;
        __syncthreads();

        // full-width reduce: warp w owns pixel w (16 warps = 16 pixels),
        // lane l reads group-l partial; 5-step butterfly; lane 0 classifies.
        {
            const int w = t >> 5, l = t & 31;
            float ax = red_x[l * RPAD + w];   // stride 17 (odd): conflict-free
            float ay = red_y[l * RPAD + w];
            float az = red_z[l * RPAD + w];
            float aw = red_w[l * RPAD + w];
            #pragma unroll
            for (int m = 1; m <= 16; m <<= 1) {
                ax += __shfl_xor_sync(0xffffffffu, ax, m);
                ay += __shfl_xor_sync(0xffffffffu, ay, m);
                az += __shfl_xor_sync(0xffffffffu, az, m);
                aw += __shfl_xor_sync(0xffffffffu, aw, m);
            }
            if (l == 0) {
                const float inv = 1.0f / (float)CH;
                float4 sv = make_float4(ax * inv, ay * inv, az * inv, aw * inv);
                int4 iv = make_int4(0, 0, 0, 0);
                #pragma unroll
                for (int k = 0; k < HID; k++) {
                    const float tk = us[k];
                    iv.x += (sv.x > tk); iv.y += (sv.y > tk);
                    iv.z += (sv.z > tk); iv.w += (sv.w > tk);
                }
                s4b[w] = sv; i4b[w] = iv;
            }
        }
        __syncthreads();

        // pass 2: compute from registers + smem table, streaming store
        const float4 sv = s4b[q];
        const int4   iv = i4b[q];
        #pragma unroll
        for (int j = 0; j < CPT; j++) {
            const int c = g + j * NGRP;
            const float2* row = AB + c * 17;
            const float2 a0 = row[iv.x], a1 = row[iv.y],
                         a2 = row[iv.z], a3 = row[iv.w];
            const float z0 = fmaf(a0.x, sv.x, a0.y);
            const float z1 = fmaf(a1.x, sv.y, a1.y);
            const float z2 = fmaf(a2.x, sv.z, a2.y);
            const float z3 = fmaf(a3.x, sv.w, a3.y);
            float4 o;
            o.x = __fdividef(v[j].x, 1.0f + __expf(-z0));
            o.y = __fdividef(v[j].y, 1.0f + __expf(-z1));
            o.z = __fdividef(v[j].z, 1.0f + __expf(-z2));
            o.w = __fdividef(v[j].w, 1.0f + __expf(-z3));
            __stcs(&out[off0 + (unsigned)j * (NGRP * HW4)], o);
        }
        // next tile's smem writes are fenced by its own __syncthreads()
    }
}

extern "C" void kernel_launch(void* const* d_in, const int* in_sizes, int n_in,
                              void* d_out, int out_size)
{
    pse_fused_kernel<<<GRID, TPB>>>((const float4*)d_in[0],
                                    (const float*)d_in[1],
                                    (const float*)d_in[2],
                                    (const float*)d_in[3],
                                    (const float*)d_in[4],
                                    (float4*)d_out);
}